// round 12
// baseline (speedup 1.0000x reference)
#include <cuda_runtime.h>

// GaussianSampler: R[b,c] = sum_{y,x} X[b,c,y,x] * gx[c,x] * gy[c,y]
// with the norm (sqrt(2*pi)*sx*sy*H*W/4) folded into gy.
// Separable weights: 64+64 __expf per block; one block per (b,c) tile,
// 32768 blocks x 256 threads, pure 512 MiB HBM stream.
//
// CONVERGED: 11 rounds established this structure hits the measured chip
// LTS ceiling (~7.0 TB/s; 76.5-77.4 us run-to-run). R12 only trims the
// s_scale broadcast/branch/multiply from the epilogue (noise-level delta).

#define NCH 1024
#define HH  64
#define WW  64

__global__ __launch_bounds__(256, 8)
void gaussian_sampler_kernel(
    const float* __restrict__ X,     // [B, C, H, W]
    const float* __restrict__ wx,    // [C]
    const float* __restrict__ wy,    // [C]
    const float* __restrict__ wsx,   // [C]
    const float* __restrict__ wsy,   // [C]
    float* __restrict__ out)         // [B, C]
{
    const int blk = blockIdx.x;          // = b*NCH + c
    const int c   = blk & (NCH - 1);

    __shared__ float gx[WW];
    __shared__ float gy[HH];             // norm scale folded in
    __shared__ float red[8];

    const int t = threadIdx.x;

    // coords: linspace(-63/64, 63/64, 64) -> coord[i] = -0.984375 + i/32
    if (t < 64) {
        float s = wsx[c];
        float d = (-0.984375f + (float)t * 0.03125f) - wx[c];
        gx[t] = __expf(-d * d / (2.0f * s * s));
    } else if (t < 128) {
        int i = t - 64;
        float sy = wsy[c];
        float sx = wsx[c];
        float d = (-0.984375f + (float)i * 0.03125f) - wy[c];
        // fold 1/(sqrt(2*pi)*sx*sy*1024) into gy
        float scale = 1.0f / (2.5066282746310002f * sx * sy * 1024.0f);
        gy[i] = __expf(-d * d / (2.0f * sy * sy)) * scale;
    }
    __syncthreads();

    // Each block reads its contiguous 16 KiB tile: X + blk*4096 floats.
    const float4* __restrict__ xp =
        reinterpret_cast<const float4*>(X + (size_t)blk * (HH * WW));

    float acc = 0.0f;
    #pragma unroll
    for (int it = 0; it < 4; it++) {
        int j = t + it * 256;            // float4 index in [0, 1024)
        float4 v = xp[j];
        int lin = j << 2;                // float index
        int y = lin >> 6;                // row
        int x = lin & 63;                // col (multiple of 4)
        float gyv = gy[y];
        acc += gyv * (v.x * gx[x] + v.y * gx[x + 1] +
                      v.z * gx[x + 2] + v.w * gx[x + 3]);
    }

    // Intra-warp reduce
    #pragma unroll
    for (int off = 16; off > 0; off >>= 1)
        acc += __shfl_down_sync(0xffffffffu, acc, off);

    if ((t & 31) == 0) red[t >> 5] = acc;
    __syncthreads();

    if (t < 8) {
        float v = red[t];
        #pragma unroll
        for (int off = 4; off > 0; off >>= 1)
            v += __shfl_down_sync(0x000000ffu, v, off);
        if (t == 0) out[blk] = v;
    }
}

extern "C" void kernel_launch(void* const* d_in, const int* in_sizes, int n_in,
                              void* d_out, int out_size) {
    // metadata order: X, wx, wy, wsigmax, wsigmay, mask
    const float* X   = (const float*)d_in[0];
    const float* wx  = (const float*)d_in[1];
    const float* wy  = (const float*)d_in[2];
    const float* wsx = (const float*)d_in[3];
    const float* wsy = (const float*)d_in[4];
    // mask (d_in[5]) is all-true by construction; nonzero(size=C) gather is identity.
    float* out = (float*)d_out;

    const int B = in_sizes[0] / (NCH * HH * WW);   // 32
    const int nblocks = B * NCH;                   // 32768

    gaussian_sampler_kernel<<<nblocks, 256>>>(X, wx, wy, wsx, wsy, out);
}

// round 13
// speedup vs baseline: 1.0257x; 1.0257x over previous
#include <cuda_runtime.h>

// GaussianSampler: R[b,c] = sum_{y,x} X[b,c,y,x] * exp(-(xs[x]-wx_c)^2/(2 sx^2))
//                                     * exp(-(ys[y]-wy_c)^2/(2 sy^2)) / norm
// norm = sqrt(2*pi) * sx * sy * H*W/4
// Separable weights: 64+64 __expf per block instead of 4096.
// Grid: one block per (b,c) pair = 32*1024 = 32768 blocks. Pure HBM stream of X (512 MiB).
//
// FINAL (== R11, session best 76.5us @ 7062 GB/s). 12 rounds established:
// runtime == 512 MiB / measured chip LTS ceiling (~7.0 TB/s). Falsified
// levers: batch amortization, per-thread weights, L2 prefetch, MLP
// front-batching, 2-channel blocks, __ldcs, cp.async pipeline (-36%).
// The ~88% DRAM duty reading is the LTS-vs-DRAM-spec gap, not slack.

#define NCH 1024
#define HH  64
#define WW  64

__global__ __launch_bounds__(256, 8)
void gaussian_sampler_kernel(
    const float* __restrict__ X,     // [B, C, H, W]
    const float* __restrict__ wx,    // [C]
    const float* __restrict__ wy,    // [C]
    const float* __restrict__ wsx,   // [C]
    const float* __restrict__ wsy,   // [C]
    float* __restrict__ out)         // [B, C]
{
    const int blk = blockIdx.x;          // = b*NCH + c
    const int c   = blk & (NCH - 1);

    __shared__ float gx[WW];
    __shared__ float gy[HH];
    __shared__ float s_scale;
    __shared__ float red[8];

    const int t = threadIdx.x;

    // coords: linspace(-63/64, 63/64, 64) -> coord[i] = -63/64 + i/32
    if (t < 64) {
        float s = wsx[c];
        float coord = -0.984375f + (float)t * 0.03125f;
        float d = coord - wx[c];
        gx[t] = __expf(-d * d / (2.0f * s * s));
    } else if (t < 128) {
        int i = t - 64;
        float s = wsy[c];
        float coord = -0.984375f + (float)i * 0.03125f;
        float d = coord - wy[c];
        gy[i] = __expf(-d * d / (2.0f * s * s));
    } else if (t == 128) {
        // 1 / (sqrt(2*pi) * sx * sy * H*W/4),  H*W/4 = 1024
        s_scale = 1.0f / (2.5066282746310002f * wsx[c] * wsy[c] * 1024.0f);
    }
    __syncthreads();

    // Each block reads its contiguous 16 KiB tile: X + blk*4096 floats.
    const float4* __restrict__ xp =
        reinterpret_cast<const float4*>(X + (size_t)blk * (HH * WW));

    float acc = 0.0f;
    #pragma unroll
    for (int it = 0; it < 4; it++) {
        int j = t + it * 256;            // float4 index in [0, 1024)
        float4 v = xp[j];
        int lin = j << 2;                // float index
        int y = lin >> 6;                // row
        int x = lin & 63;                // col (multiple of 4)
        float gyv = gy[y];
        acc += gyv * (v.x * gx[x] + v.y * gx[x + 1] +
                      v.z * gx[x + 2] + v.w * gx[x + 3]);
    }

    // Intra-warp reduce
    #pragma unroll
    for (int off = 16; off > 0; off >>= 1)
        acc += __shfl_down_sync(0xffffffffu, acc, off);

    if ((t & 31) == 0) red[t >> 5] = acc;
    __syncthreads();

    if (t < 8) {
        float v = red[t];
        #pragma unroll
        for (int off = 4; off > 0; off >>= 1)
            v += __shfl_down_sync(0x000000ffu, v, off);
        if (t == 0) out[blk] = v * s_scale;
    }
}

extern "C" void kernel_launch(void* const* d_in, const int* in_sizes, int n_in,
                              void* d_out, int out_size) {
    // metadata order: X, wx, wy, wsigmax, wsigmay, mask
    const float* X   = (const float*)d_in[0];
    const float* wx  = (const float*)d_in[1];
    const float* wy  = (const float*)d_in[2];
    const float* wsx = (const float*)d_in[3];
    const float* wsy = (const float*)d_in[4];
    // mask (d_in[5]) is all-true by construction; nonzero(size=C) gather is identity.
    float* out = (float*)d_out;

    const int B = in_sizes[0] / (NCH * HH * WW);   // 32
    const int nblocks = B * NCH;                   // 32768

    gaussian_sampler_kernel<<<nblocks, 256>>>(X, wx, wy, wsx, wsy, out);
}